// round 7
// baseline (speedup 1.0000x reference)
#include <cuda_runtime.h>
#include <math.h>

#define Bn 32
#define Tn 512
#define Hn 2048
#define Kn 128

// Scratch (no allocations allowed)
__device__ float g_logits[Bn * Tn * Kn];   // 8 MB
__device__ float g_scores[Bn * Tn * Kn];   // 8 MB viterbi score rows
__device__ float g_llh[Bn];

// ---------------------------------------------------------------------------
// GEMM: logits[m][n] = sum_h hiddens[m][h] * W[h][n] + b[n]   (R1 config)
// BM=64, BN=128, BK=16, 256 threads, 8x4 per-thread tile.
// ---------------------------------------------------------------------------
__global__ __launch_bounds__(256) void gemm_kernel(
    const float* __restrict__ hid, const float* __restrict__ W,
    const float* __restrict__ bias)
{
    __shared__ float As[16][64];
    __shared__ float Bs[16][128];

    const int tid = threadIdx.x;
    const int m0  = blockIdx.x * 64;
    const int ty  = tid >> 5;
    const int tx  = tid & 31;

    float acc[8][4];
#pragma unroll
    for (int i = 0; i < 8; i++)
#pragma unroll
        for (int jj = 0; jj < 4; jj++) acc[i][jj] = 0.f;

    const int arow = tid >> 2;
    const int ac4  = (tid & 3) * 4;

    for (int k0 = 0; k0 < Hn; k0 += 16) {
        float4 a4 = *(const float4*)(hid + (size_t)(m0 + arow) * Hn + k0 + ac4);
        As[ac4 + 0][arow] = a4.x;
        As[ac4 + 1][arow] = a4.y;
        As[ac4 + 2][arow] = a4.z;
        As[ac4 + 3][arow] = a4.w;
        {
            int idx = tid;
            int r = idx >> 5, c = (idx & 31) * 4;
            *(float4*)(&Bs[r][c]) = *(const float4*)(W + (size_t)(k0 + r) * Kn + c);
            idx = tid + 256;
            r = idx >> 5; c = (idx & 31) * 4;
            *(float4*)(&Bs[r][c]) = *(const float4*)(W + (size_t)(k0 + r) * Kn + c);
        }
        __syncthreads();

#pragma unroll
        for (int k = 0; k < 16; k++) {
            float4 b4 = *(const float4*)(&Bs[k][tx * 4]);
            float a[8];
#pragma unroll
            for (int i = 0; i < 8; i++) a[i] = As[k][ty * 8 + i];
#pragma unroll
            for (int i = 0; i < 8; i++) {
                acc[i][0] += a[i] * b4.x;
                acc[i][1] += a[i] * b4.y;
                acc[i][2] += a[i] * b4.z;
                acc[i][3] += a[i] * b4.w;
            }
        }
        __syncthreads();
    }

    const int n0 = tx * 4;
    float4 bb = *(const float4*)(bias + n0);
#pragma unroll
    for (int i = 0; i < 8; i++) {
        int row = m0 + ty * 8 + i;
        float4 o;
        o.x = acc[i][0] + bb.x;
        o.y = acc[i][1] + bb.y;
        o.z = acc[i][2] + bb.z;
        o.w = acc[i][3] + bb.w;
        *(float4*)(g_logits + (size_t)row * Kn + n0) = o;
    }
}

// ---------------------------------------------------------------------------
// CRF phase 1. 64 blocks x 256 threads, tiny static smem.
// blocks [0,32): forward logsumexp (lagged shift) + path score -> g_llh[b]
// blocks [32,64): viterbi VALUE-ONLY recurrence -> g_scores rows
// j = tid>>1 (tag), h = tid&1 (source half).
// ---------------------------------------------------------------------------
__global__ __launch_bounds__(256) void crf_kernel(
    const int* __restrict__ mask, const int* __restrict__ labels,
    const float* __restrict__ startT, const float* __restrict__ endT,
    const float* __restrict__ trans)
{
    __shared__ float sbuf[2][Kn];
    __shared__ float msh[2];      // shift per buffer (forward)
    __shared__ float sa0[2];      // alpha_0 per buffer (forward)
    __shared__ float shred[8];
    __shared__ int   shredi[8];

    const int tid = threadIdx.x;
    const int j = tid >> 1, h = tid & 1;
    const unsigned FULL = 0xFFFFFFFFu;
    const int bidx = blockIdx.x;

    if (bidx < Bn) {
        // ================= FORWARD =================
        const int b = bidx;
        float Eh[64];
#pragma unroll
        for (int i = 0; i < 64; i++)
            Eh[i] = __expf(trans[(h * 64 + i) * Kn + j]);

        const float* lg = g_logits + (size_t)b * Tn * Kn;
        float alpha = startT[j] + lg[j];
        float c0 = startT[0] + lg[0];              // uniform across threads
        if (h == 0) sbuf[0][j] = __expf(alpha - c0);
        if (tid == 0) { msh[0] = c0; sa0[0] = alpha; }
        float e_next = lg[Kn + j];
        __syncthreads();

        for (int t = 1; t < Tn; t++) {
            const int cur = (t - 1) & 1, nb = t & 1;
            float C  = msh[cur];
            float A0 = sa0[cur];
            float emit = e_next;
            if (t + 1 < Tn) e_next = lg[(size_t)(t + 1) * Kn + j];
            int mt = mask[b * Tn + t];

            // s = sum_i p_i * E_ij   (4 independent accumulators)
            const float4* p4 = (const float4*)(&sbuf[cur][h * 64]);
            float s0 = 0.f, s1 = 0.f, s2 = 0.f, s3 = 0.f;
#pragma unroll
            for (int g = 0; g < 4; g++) {
                float4 va = p4[4 * g + 0];
                float4 vb = p4[4 * g + 1];
                float4 vc = p4[4 * g + 2];
                float4 vd = p4[4 * g + 3];
                s0 += va.x * Eh[16 * g + 0];  s0 += va.y * Eh[16 * g + 1];
                s0 += va.z * Eh[16 * g + 2];  s0 += va.w * Eh[16 * g + 3];
                s1 += vb.x * Eh[16 * g + 4];  s1 += vb.y * Eh[16 * g + 5];
                s1 += vb.z * Eh[16 * g + 6];  s1 += vb.w * Eh[16 * g + 7];
                s2 += vc.x * Eh[16 * g + 8];  s2 += vc.y * Eh[16 * g + 9];
                s2 += vc.z * Eh[16 * g + 10]; s2 += vc.w * Eh[16 * g + 11];
                s3 += vd.x * Eh[16 * g + 12]; s3 += vd.y * Eh[16 * g + 13];
                s3 += vd.z * Eh[16 * g + 14]; s3 += vd.w * Eh[16 * g + 15];
            }
            float s = (s0 + s1) + (s2 + s3);
            s += __shfl_xor_sync(FULL, s, 1);

            float nxt = C + __logf(s) + emit;
            alpha = (mt > 0) ? nxt : alpha;

            float cn = A0;                    // lagged shift
            if (h == 0) sbuf[nb][j] = __expf(alpha - cn);
            if (tid == 0) { msh[nb] = cn; sa0[nb] = alpha; }
            __syncthreads();
        }

        // logZ = logsumexp_j(alpha_j + end_j)
        float v = alpha + endT[j];
        float wm = v;
#pragma unroll
        for (int o = 16; o; o >>= 1)
            wm = fmaxf(wm, __shfl_xor_sync(FULL, wm, o));
        if ((tid & 31) == 0) shred[tid >> 5] = wm;
        __syncthreads();
        float m = shred[0];
#pragma unroll
        for (int w = 1; w < 8; w++) m = fmaxf(m, shred[w]);
        __syncthreads();
        float pc = (h == 0) ? __expf(v - m) : 0.f;
#pragma unroll
        for (int o = 16; o; o >>= 1)
            pc += __shfl_xor_sync(FULL, pc, o);
        if ((tid & 31) == 0) shred[tid >> 5] = pc;
        __syncthreads();
        float Z = 0.f;
#pragma unroll
        for (int w = 0; w < 8; w++) Z += shred[w];
        float logZ = m + __logf(Z);
        __syncthreads();

        // path score
        float sc = 0.f;
        int msum = 0;
        for (int t = tid; t < Tn; t += 256) {
            msum += mask[b * Tn + t];
            if (t >= 1) {
                int cur  = labels[b * Tn + t];
                int prev = labels[b * Tn + t - 1];
                float mf = (float)mask[b * Tn + t];
                sc += (trans[prev * Kn + cur] + lg[(size_t)t * Kn + cur]) * mf;
            }
        }
#pragma unroll
        for (int o = 16; o; o >>= 1) {
            sc   += __shfl_xor_sync(FULL, sc, o);
            msum += __shfl_xor_sync(FULL, msum, o);
        }
        if ((tid & 31) == 0) { shred[tid >> 5] = sc; shredi[tid >> 5] = msum; }
        __syncthreads();
        if (tid == 0) {
            float S = 0.f; int Mc = 0;
#pragma unroll
            for (int w = 0; w < 8; w++) { S += shred[w]; Mc += shredi[w]; }
            int l0 = labels[b * Tn];
            S += startT[l0] + lg[l0];
            int last = labels[b * Tn + (Mc - 1)];
            S += endT[last];
            g_llh[b] = S - logZ;
        }
    } else {
        // ================= VITERBI (value-only) =================
        const int b = bidx - Bn;
        float Th[64];
#pragma unroll
        for (int i = 0; i < 64; i++)
            Th[i] = trans[(h * 64 + i) * Kn + j];

        const float* lg = g_logits + (size_t)b * Tn * Kn;
        float* gs = g_scores + (size_t)b * Tn * Kn;
        float sj = startT[j] + lg[j];
        if (h == 0) { sbuf[0][j] = sj; gs[j] = sj; }
        float e_next = lg[Kn + j];
        __syncthreads();

        for (int t = 1; t < Tn; t++) {
            const int cur = (t - 1) & 1, nb = t & 1;
            float emit = e_next;
            if (t + 1 < Tn) e_next = lg[(size_t)(t + 1) * Kn + j];
            int mt = mask[b * Tn + t];

            const float4* s4 = (const float4*)(&sbuf[cur][h * 64]);
            float best = -3.4e38f;
#pragma unroll
            for (int g = 0; g < 4; g++) {
                float4 va = s4[4 * g + 0];
                float4 vb = s4[4 * g + 1];
                float4 vc = s4[4 * g + 2];
                float4 vd = s4[4 * g + 3];
                float m0 = fmaxf(fmaxf(va.x + Th[16 * g + 0],  va.y + Th[16 * g + 1]),
                                 fmaxf(va.z + Th[16 * g + 2],  va.w + Th[16 * g + 3]));
                float m1 = fmaxf(fmaxf(vb.x + Th[16 * g + 4],  vb.y + Th[16 * g + 5]),
                                 fmaxf(vb.z + Th[16 * g + 6],  vb.w + Th[16 * g + 7]));
                float m2 = fmaxf(fmaxf(vc.x + Th[16 * g + 8],  vc.y + Th[16 * g + 9]),
                                 fmaxf(vc.z + Th[16 * g + 10], vc.w + Th[16 * g + 11]));
                float m3 = fmaxf(fmaxf(vd.x + Th[16 * g + 12], vd.y + Th[16 * g + 13]),
                                 fmaxf(vd.z + Th[16 * g + 14], vd.w + Th[16 * g + 15]));
                best = fmaxf(best, fmaxf(fmaxf(m0, m1), fmaxf(m2, m3)));
            }
            best = fmaxf(best, __shfl_xor_sync(FULL, best, 1));

            sj = (mt > 0) ? (best + emit) : sj;
            if (h == 0) {
                sbuf[nb][j] = sj;
                gs[(size_t)t * Kn + j] = sj;
            }
            __syncthreads();
        }
    }
}

// ---------------------------------------------------------------------------
// Backtrace: 32 blocks x 256 threads. Loads trans transposed into smem,
// then warp 0 re-derives the 511 on-path argmaxes with exact reference
// tie semantics (first index wins).
// ---------------------------------------------------------------------------
#define TT_PITCH 132
#define BT_SMEM (Kn * TT_PITCH * 4)

__global__ __launch_bounds__(256) void backtrace_kernel(
    const int* __restrict__ mask, const float* __restrict__ endT,
    const float* __restrict__ trans, float* __restrict__ out)
{
    extern __shared__ float Tt[];   // Tt[j * TT_PITCH + i] = trans[i][j]
    const int tid = threadIdx.x;
    const int b = blockIdx.x;
    const unsigned FULL = 0xFFFFFFFFu;

    for (int idx = tid; idx < Kn * Kn; idx += 256) {
        int i = idx >> 7, jj = idx & 127;
        Tt[jj * TT_PITCH + i] = trans[i * Kn + jj];
    }
    __syncthreads();

    if (tid < 32) {
        const int lane = tid;
        const float* gs = g_scores + (size_t)b * Tn * Kn;
        const int i0 = lane * 4;

        // last tag: argmax_j( score(T-1)_j + end_j ), first-index ties
        float4 sr = *(const float4*)(gs + (size_t)(Tn - 1) * Kn + i0);
        float4 er = *(const float4*)(endT + i0);
        float c0 = sr.x + er.x, c1 = sr.y + er.y;
        float c2 = sr.z + er.z, c3 = sr.w + er.w;
        float bv = c0; int bi = i0;
        if (c1 > bv) { bv = c1; bi = i0 + 1; }
        if (c2 > bv) { bv = c2; bi = i0 + 2; }
        if (c3 > bv) { bv = c3; bi = i0 + 3; }
#pragma unroll
        for (int o = 16; o; o >>= 1) {
            float ov = __shfl_xor_sync(FULL, bv, o);
            int   oi = __shfl_xor_sync(FULL, bi, o);
            if (ov > bv || (ov == bv && oi < bi)) { bv = ov; bi = oi; }
        }
        int tag = bi;
        if (lane == 0) out[b * Tn + (Tn - 1)] = (float)tag;

        // prefetch score row Tn-2
        float4 s_next = *(const float4*)(gs + (size_t)(Tn - 2) * Kn + i0);

        for (int t = Tn - 1; t >= 1; t--) {
            float4 srow = s_next;
            if (t >= 2)
                s_next = *(const float4*)(gs + (size_t)(t - 2) * Kn + i0);
            int mt = mask[b * Tn + t];
            if (mt > 0) {
                float4 t4 = *(const float4*)(&Tt[tag * TT_PITCH + i0]);
                float d0 = srow.x + t4.x, d1 = srow.y + t4.y;
                float d2 = srow.z + t4.z, d3 = srow.w + t4.w;
                float v = d0; int vi = i0;
                if (d1 > v) { v = d1; vi = i0 + 1; }
                if (d2 > v) { v = d2; vi = i0 + 2; }
                if (d3 > v) { v = d3; vi = i0 + 3; }
#pragma unroll
                for (int o = 16; o; o >>= 1) {
                    float ov = __shfl_xor_sync(FULL, v, o);
                    int   oi = __shfl_xor_sync(FULL, vi, o);
                    if (ov > v || (ov == v && oi < vi)) { v = ov; vi = oi; }
                }
                tag = vi;
            }
            // else: bp row is identity -> tag unchanged
            if (lane == 0) out[b * Tn + (t - 1)] = (float)tag;
        }
    }
}

// ---------------------------------------------------------------------------
// loss = -mean(llh)
// ---------------------------------------------------------------------------
__global__ void loss_kernel(float* __restrict__ out)
{
    const unsigned FULL = 0xFFFFFFFFu;
    float v = (threadIdx.x < Bn) ? g_llh[threadIdx.x] : 0.f;
#pragma unroll
    for (int o = 16; o; o >>= 1) v += __shfl_xor_sync(FULL, v, o);
    if (threadIdx.x == 0) out[Bn * Tn] = -(v / (float)Bn);
}

extern "C" void kernel_launch(void* const* d_in, const int* in_sizes, int n_in,
                              void* d_out, int out_size)
{
    const float* hiddens = (const float*)d_in[0];
    const int*   mask    = (const int*)d_in[1];
    const int*   labels  = (const int*)d_in[2];
    const float* W       = (const float*)d_in[3];
    const float* bias    = (const float*)d_in[4];
    const float* startT  = (const float*)d_in[5];
    const float* endT    = (const float*)d_in[6];
    const float* trans   = (const float*)d_in[7];
    float* out = (float*)d_out;

    gemm_kernel<<<(Bn * Tn) / 64, 256>>>(hiddens, W, bias);

    crf_kernel<<<2 * Bn, 256>>>(mask, labels, startT, endT, trans);

    cudaFuncSetAttribute(backtrace_kernel,
                         cudaFuncAttributeMaxDynamicSharedMemorySize, BT_SMEM);
    backtrace_kernel<<<Bn, 256, BT_SMEM>>>(mask, endT, trans, out);

    loss_kernel<<<1, 32>>>(out);
}

// round 9
// speedup vs baseline: 1.2152x; 1.2152x over previous
#include <cuda_runtime.h>
#include <math.h>

#define Bn 32
#define Tn 512
#define Hn 2048
#define Kn 128

// Scratch (no allocations allowed)
__device__ float g_logits[Bn * Tn * Kn];   // 8 MB
__device__ float g_llh[Bn];

// ---------------------------------------------------------------------------
// GEMM: logits[m][n] = sum_h hiddens[m][h] * W[h][n] + b[n]   (R1 config)
// BM=64, BN=128, BK=16, 256 threads, 8x4 per-thread tile.
// ---------------------------------------------------------------------------
__global__ __launch_bounds__(256) void gemm_kernel(
    const float* __restrict__ hid, const float* __restrict__ W,
    const float* __restrict__ bias)
{
    __shared__ float As[16][64];
    __shared__ float Bs[16][128];

    const int tid = threadIdx.x;
    const int m0  = blockIdx.x * 64;
    const int ty  = tid >> 5;
    const int tx  = tid & 31;

    float acc[8][4];
#pragma unroll
    for (int i = 0; i < 8; i++)
#pragma unroll
        for (int jj = 0; jj < 4; jj++) acc[i][jj] = 0.f;

    const int arow = tid >> 2;
    const int ac4  = (tid & 3) * 4;

    for (int k0 = 0; k0 < Hn; k0 += 16) {
        float4 a4 = *(const float4*)(hid + (size_t)(m0 + arow) * Hn + k0 + ac4);
        As[ac4 + 0][arow] = a4.x;
        As[ac4 + 1][arow] = a4.y;
        As[ac4 + 2][arow] = a4.z;
        As[ac4 + 3][arow] = a4.w;
        {
            int idx = tid;
            int r = idx >> 5, c = (idx & 31) * 4;
            *(float4*)(&Bs[r][c]) = *(const float4*)(W + (size_t)(k0 + r) * Kn + c);
            idx = tid + 256;
            r = idx >> 5; c = (idx & 31) * 4;
            *(float4*)(&Bs[r][c]) = *(const float4*)(W + (size_t)(k0 + r) * Kn + c);
        }
        __syncthreads();

#pragma unroll
        for (int k = 0; k < 16; k++) {
            float4 b4 = *(const float4*)(&Bs[k][tx * 4]);
            float a[8];
#pragma unroll
            for (int i = 0; i < 8; i++) a[i] = As[k][ty * 8 + i];
#pragma unroll
            for (int i = 0; i < 8; i++) {
                acc[i][0] += a[i] * b4.x;
                acc[i][1] += a[i] * b4.y;
                acc[i][2] += a[i] * b4.z;
                acc[i][3] += a[i] * b4.w;
            }
        }
        __syncthreads();
    }

    const int n0 = tx * 4;
    float4 bb = *(const float4*)(bias + n0);
#pragma unroll
    for (int i = 0; i < 8; i++) {
        int row = m0 + ty * 8 + i;
        float4 o;
        o.x = acc[i][0] + bb.x;
        o.y = acc[i][1] + bb.y;
        o.z = acc[i][2] + bb.z;
        o.w = acc[i][3] + bb.w;
        *(float4*)(g_logits + (size_t)row * Kn + n0) = o;
    }
}

// ---------------------------------------------------------------------------
// CRF recurrences. 64 blocks x 256 threads.
// blocks [0,32): forward logsumexp (lagged-alpha0 shift, 1 barrier/step)
// blocks [32,64): viterbi decode (EXACT R1 code) -> out tags
// j = tid>>1 (tag), h = tid&1 (source half).
// ---------------------------------------------------------------------------
#define SMEM_BYTES (1024 + (Tn - 1) * Kn)

__global__ __launch_bounds__(256) void crf_kernel(
    const int* __restrict__ mask, const int* __restrict__ labels,
    const float* __restrict__ startT, const float* __restrict__ endT,
    const float* __restrict__ trans, float* __restrict__ out)
{
    extern __shared__ char smem[];
    const int tid = threadIdx.x;
    const int j = tid >> 1, h = tid & 1;
    const unsigned FULL = 0xFFFFFFFFu;
    const int bidx = blockIdx.x;

    if (bidx < Bn) {
        // ================= FORWARD =================
        // smem: [0,1024) p2[2][128] | [1024,1032) sC[2] | [1032,1040) sa0[2]
        //       [1056,1088) shred[8] | [1088,1120) shredi[8]
        float* p2    = (float*)smem;
        float* sC    = (float*)(smem + 1024);
        float* sa0   = (float*)(smem + 1032);
        float* shred = (float*)(smem + 1056);
        int*   shredi= (int*)(smem + 1088);

        const int b = bidx;
        float Eh[64];
#pragma unroll
        for (int i = 0; i < 64; i++)
            Eh[i] = __expf(trans[(h * 64 + i) * Kn + j]);

        const float* lg = g_logits + (size_t)b * Tn * Kn;
        float alpha = startT[j] + lg[j];
        float C0 = startT[0] + lg[0];            // uniform across threads
        if (h == 0) p2[j] = __expf(alpha - C0);
        if (tid == 0) { sC[0] = C0; sa0[0] = alpha; }   // tid0 has j=0
        float e_next = lg[Kn + j];
        __syncthreads();

        for (int t = 1; t < Tn; t++) {
            const int cur = (t - 1) & 1, nb = t & 1;
            float Cu = sC[cur];                   // shift under which p was written
            float A0 = sa0[cur];                  // next shift (lagged alpha_0)
            float emit = e_next;
            if (t + 1 < Tn) e_next = lg[(size_t)(t + 1) * Kn + j];
            int mt = mask[b * Tn + t];

            const float4* p4 = (const float4*)(p2 + cur * Kn + h * 64);
            float s0 = 0.f, s1 = 0.f, s2 = 0.f, s3 = 0.f;
#pragma unroll
            for (int g = 0; g < 4; g++) {
                float4 va = p4[4 * g + 0];
                float4 vb = p4[4 * g + 1];
                float4 vc = p4[4 * g + 2];
                float4 vd = p4[4 * g + 3];
                s0 += va.x * Eh[16 * g + 0];  s0 += va.y * Eh[16 * g + 1];
                s0 += va.z * Eh[16 * g + 2];  s0 += va.w * Eh[16 * g + 3];
                s1 += vb.x * Eh[16 * g + 4];  s1 += vb.y * Eh[16 * g + 5];
                s1 += vb.z * Eh[16 * g + 6];  s1 += vb.w * Eh[16 * g + 7];
                s2 += vc.x * Eh[16 * g + 8];  s2 += vc.y * Eh[16 * g + 9];
                s2 += vc.z * Eh[16 * g + 10]; s2 += vc.w * Eh[16 * g + 11];
                s3 += vd.x * Eh[16 * g + 12]; s3 += vd.y * Eh[16 * g + 13];
                s3 += vd.z * Eh[16 * g + 14]; s3 += vd.w * Eh[16 * g + 15];
            }
            float s = (s0 + s1) + (s2 + s3);
            s += __shfl_xor_sync(FULL, s, 1);

            float nxt = Cu + __logf(s) + emit;
            alpha = (mt > 0) ? nxt : alpha;

            if (h == 0) p2[nb * Kn + j] = __expf(alpha - A0);
            if (tid == 0) { sC[nb] = A0; sa0[nb] = alpha; }
            __syncthreads();
        }

        // logZ = logsumexp_j(alpha_j + end_j)  (exact reduce)
        float v = alpha + endT[j];
        float wm = v;
#pragma unroll
        for (int o = 16; o; o >>= 1)
            wm = fmaxf(wm, __shfl_xor_sync(FULL, wm, o));
        if ((tid & 31) == 0) shred[tid >> 5] = wm;
        __syncthreads();
        float m = shred[0];
#pragma unroll
        for (int w = 1; w < 8; w++) m = fmaxf(m, shred[w]);
        __syncthreads();
        float pc = (h == 0) ? __expf(v - m) : 0.f;
#pragma unroll
        for (int o = 16; o; o >>= 1)
            pc += __shfl_xor_sync(FULL, pc, o);
        if ((tid & 31) == 0) shred[tid >> 5] = pc;
        __syncthreads();
        float Z = 0.f;
#pragma unroll
        for (int w = 0; w < 8; w++) Z += shred[w];
        float logZ = m + __logf(Z);
        __syncthreads();

        // path score
        float sc = 0.f;
        int msum = 0;
        for (int t = tid; t < Tn; t += 256) {
            msum += mask[b * Tn + t];
            if (t >= 1) {
                int cur  = labels[b * Tn + t];
                int prev = labels[b * Tn + t - 1];
                float mf = (float)mask[b * Tn + t];
                sc += (trans[prev * Kn + cur] + lg[(size_t)t * Kn + cur]) * mf;
            }
        }
#pragma unroll
        for (int o = 16; o; o >>= 1) {
            sc   += __shfl_xor_sync(FULL, sc, o);
            msum += __shfl_xor_sync(FULL, msum, o);
        }
        if ((tid & 31) == 0) { shred[tid >> 5] = sc; shredi[tid >> 5] = msum; }
        __syncthreads();
        if (tid == 0) {
            float S = 0.f; int Mc = 0;
#pragma unroll
            for (int w = 0; w < 8; w++) { S += shred[w]; Mc += shredi[w]; }
            int l0 = labels[b * Tn];
            S += startT[l0] + lg[l0];
            int last = labels[b * Tn + (Mc - 1)];
            S += endT[last];
            g_llh[b] = S - logZ;
        }
    } else {
        // ================= VITERBI (exact R1 code) =================
        float* sh_s   = (float*)smem;                 // 128 floats
        float* shred  = (float*)(smem + 512);
        unsigned char* bp = (unsigned char*)(smem + 1024);

        const int b = bidx - Bn;
        float Th[64];
#pragma unroll
        for (int i = 0; i < 64; i++)
            Th[i] = trans[(h * 64 + i) * Kn + j];

        const float* lg = g_logits + (size_t)b * Tn * Kn;
        float sj = startT[j] + lg[j];
        if (h == 0) sh_s[j] = sj;
        float e_next = lg[Kn + j];
        __syncthreads();

        for (int t = 1; t < Tn; t++) {
            float emit = e_next;
            if (t + 1 < Tn) e_next = lg[(size_t)(t + 1) * Kn + j];
            int mt = mask[b * Tn + t];

            float best = -3.4e38f;
            int arg = 0;
            const float4* s4 = (const float4*)(sh_s + h * 64);
#pragma unroll
            for (int i4 = 0; i4 < 16; i4++) {
                float4 v = s4[i4];
                float c0 = v.x + Th[i4 * 4 + 0];
                float c1 = v.y + Th[i4 * 4 + 1];
                float c2 = v.z + Th[i4 * 4 + 2];
                float c3 = v.w + Th[i4 * 4 + 3];
                if (c0 > best) { best = c0; arg = i4 * 4 + 0; }
                if (c1 > best) { best = c1; arg = i4 * 4 + 1; }
                if (c2 > best) { best = c2; arg = i4 * 4 + 2; }
                if (c3 > best) { best = c3; arg = i4 * 4 + 3; }
            }
            int ai = h * 64 + arg;
            float ob = __shfl_xor_sync(FULL, best, 1);
            int   oi = __shfl_xor_sync(FULL, ai, 1);
            // first-index-on-tie: lower-index candidate is the h==0 one
            float lb = (h == 0) ? best : ob;
            int   li = (h == 0) ? ai   : oi;
            float hb = (h == 0) ? ob   : best;
            int   hi = (h == 0) ? oi   : ai;
            float fb; int fa;
            if (hb > lb) { fb = hb; fa = hi; } else { fb = lb; fa = li; }

            float ns; int bpv;
            if (mt > 0) { ns = fb + emit; bpv = fa; }
            else        { ns = sj;        bpv = j;  }
            sj = ns;
            __syncthreads();                       // S1 (reads done)
            if (h == 0) {
                sh_s[j] = sj;
                bp[(size_t)(t - 1) * Kn + j] = (unsigned char)bpv;
            }
            __syncthreads();                       // S2 (writes visible)
        }

        if (h == 0) sh_s[j] = sj + endT[j];
        __syncthreads();
        if (tid == 0) {
            float bbest = sh_s[0];
            int btag = 0;
            for (int q = 1; q < Kn; q++) {
                float vv = sh_s[q];
                if (vv > bbest) { bbest = vv; btag = q; }
            }
            int tag = btag;
            out[b * Tn + (Tn - 1)] = (float)tag;
            for (int t = Tn - 2; t >= 0; t--) {
                tag = bp[(size_t)t * Kn + tag];
                out[b * Tn + t] = (float)tag;
            }
        }
        (void)shred;
    }
}

// ---------------------------------------------------------------------------
// loss = -mean(llh)
// ---------------------------------------------------------------------------
__global__ void loss_kernel(float* __restrict__ out)
{
    const unsigned FULL = 0xFFFFFFFFu;
    float v = (threadIdx.x < Bn) ? g_llh[threadIdx.x] : 0.f;
#pragma unroll
    for (int o = 16; o; o >>= 1) v += __shfl_xor_sync(FULL, v, o);
    if (threadIdx.x == 0) out[Bn * Tn] = -(v / (float)Bn);
}

extern "C" void kernel_launch(void* const* d_in, const int* in_sizes, int n_in,
                              void* d_out, int out_size)
{
    const float* hiddens = (const float*)d_in[0];
    const int*   mask    = (const int*)d_in[1];
    const int*   labels  = (const int*)d_in[2];
    const float* W       = (const float*)d_in[3];
    const float* bias    = (const float*)d_in[4];
    const float* startT  = (const float*)d_in[5];
    const float* endT    = (const float*)d_in[6];
    const float* trans   = (const float*)d_in[7];
    float* out = (float*)d_out;

    gemm_kernel<<<(Bn * Tn) / 64, 256>>>(hiddens, W, bias);

    cudaFuncSetAttribute(crf_kernel, cudaFuncAttributeMaxDynamicSharedMemorySize,
                         SMEM_BYTES);
    crf_kernel<<<2 * Bn, 256, SMEM_BYTES>>>(mask, labels, startT, endT, trans, out);

    loss_kernel<<<1, 32>>>(out);
}